// round 7
// baseline (speedup 1.0000x reference)
#include <cuda_runtime.h>
#include <math_constants.h>

// Problem constants (fixed by the reference)
#define BB 2
#define TT 512
#define EE 1024
#define SS 2048
#define AA 30

#define NBINS (TT * AA)          // key = t0*30 + (w-1), 15360 bins
#define NGROUPS_MAX 1024         // sum ceil(n_t/4) <= 896
#define GSZ 4                    // spans per group

__device__ float g_scores[BB * TT];
__device__ float g_probs[BB * SS * 32];
__device__ int   g_sorted[SS];
__device__ int4  g_groups[NGROUPS_MAX];
__device__ int   g_ngroups;

// ---------------------------------------------------------------------------
// Kernel 1: scores[b,t] = relu(dot(x[b,t,:], W) + bias). Warp per row, ILP=8.
// ---------------------------------------------------------------------------
__global__ __launch_bounds__(256)
void score_kernel(const float* __restrict__ x,
                  const float* __restrict__ W,
                  const float* __restrict__ bias) {
    const int row  = blockIdx.x * 8 + (threadIdx.x >> 5);   // B*T = 1024 rows
    const int lane = threadIdx.x & 31;

    const float4* __restrict__ xr = reinterpret_cast<const float4*>(x) + (size_t)row * 256;
    const float4* __restrict__ w4 = reinterpret_cast<const float4*>(W);

    float acc = 0.0f;
#pragma unroll
    for (int i = 0; i < 8; ++i) {
        const float4 xv = xr[lane + i * 32];
        const float4 wv = w4[lane + i * 32];
        acc += xv.x * wv.x + xv.y * wv.y + xv.z * wv.z + xv.w * wv.w;
    }
#pragma unroll
    for (int off = 16; off; off >>= 1)
        acc += __shfl_xor_sync(0xffffffffu, acc, off);

    if (lane == 0)
        g_scores[row] = fmaxf(acc + bias[0], 0.0f);
}

// ---------------------------------------------------------------------------
// Kernel 2: softmax probs per (b,s) -> g_probs[b][s][lane] (0 for lane >= w).
// ---------------------------------------------------------------------------
__global__ __launch_bounds__(256)
void prob_kernel(const int* __restrict__ start,
                 const int* __restrict__ end) {
    const int wid  = blockIdx.x * 8 + (threadIdx.x >> 5);   // 0 .. B*S-1
    const int lane = threadIdx.x & 31;
    const int s = wid & (SS - 1);
    const int b = wid >> 11;

    const int t0 = start[s];
    const int w  = end[s] - t0 + 1;                          // 1..30

    float sc = (lane < w) ? g_scores[b * TT + t0 + lane] : -CUDART_INF_F;
    float m = sc;
#pragma unroll
    for (int off = 16; off; off >>= 1)
        m = fmaxf(m, __shfl_xor_sync(0xffffffffu, m, off));
    float e = (lane < w) ? __expf(sc - m) : 0.0f;
    float sum = e;
#pragma unroll
    for (int off = 16; off; off >>= 1)
        sum += __shfl_xor_sync(0xffffffffu, sum, off);

    g_probs[((size_t)b * SS + s) * 32 + lane] = e / sum;
}

// ---------------------------------------------------------------------------
// Kernel 3: counting sort of spans by key (t0, w) + group building.
// Single block, 1024 threads, bins in dynamic smem (60 KB).
// Groups of <=4 spans sharing the same t0 (consecutive w -> tight wmax).
// ---------------------------------------------------------------------------
extern __shared__ int sm_bins[];

__global__ __launch_bounds__(1024)
void sort_kernel(const int* __restrict__ start,
                 const int* __restrict__ end) {
    int* bins = sm_bins;                 // [NBINS]
    __shared__ int t0_off[TT + 1];
    __shared__ int aux[32];
    __shared__ int gcnt;

    const int tid  = threadIdx.x;
    const int lane = tid & 31;
    const int wrp  = tid >> 5;

    for (int i = tid; i < NBINS; i += 1024) bins[i] = 0;
    if (tid == 0) gcnt = 0;
    __syncthreads();

    // histogram
    for (int s = tid; s < SS; s += 1024) {
        const int t0 = start[s];
        const int w  = end[s] - t0 + 1;
        atomicAdd(&bins[t0 * AA + (w - 1)], 1);
    }
    __syncthreads();

    // exclusive scan over NBINS (chunk of 15 per thread + 2-level block scan)
    const int base = tid * (NBINS / 1024);   // 15 per thread
    int v[NBINS / 1024];
    int run = 0;
#pragma unroll
    for (int c = 0; c < NBINS / 1024; ++c) { v[c] = bins[base + c]; run += v[c]; }

    int inc = run;
#pragma unroll
    for (int off = 1; off < 32; off <<= 1) {
        const int t = __shfl_up_sync(0xffffffffu, inc, off);
        if (lane >= off) inc += t;
    }
    if (lane == 31) aux[wrp] = inc;
    __syncthreads();
    if (wrp == 0) {
        int a = aux[lane];
#pragma unroll
        for (int off = 1; off < 32; off <<= 1) {
            const int t = __shfl_up_sync(0xffffffffu, a, off);
            if (lane >= off) a += t;
        }
        aux[lane] = a;
    }
    __syncthreads();
    int ex = inc - run + (wrp ? aux[wrp - 1] : 0);
#pragma unroll
    for (int c = 0; c < NBINS / 1024; ++c) { const int t = v[c]; bins[base + c] = ex; ex += t; }
    __syncthreads();

    // snapshot per-t0 offsets before scatter mutates bins
    if (tid < TT) t0_off[tid] = bins[tid * AA];
    if (tid == 0) t0_off[TT] = SS;
    __syncthreads();

    // scatter
    for (int s = tid; s < SS; s += 1024) {
        const int t0 = start[s];
        const int w  = end[s] - t0 + 1;
        const int pos = atomicAdd(&bins[t0 * AA + (w - 1)], 1);
        g_sorted[pos] = s;
    }
    __syncthreads();

    // build groups of <=4 spans per t0
    if (tid < TT) {
        const int b0 = t0_off[tid];
        const int n  = t0_off[tid + 1] - b0;
        for (int k = 0; k < n; k += GSZ) {
            const int gi = atomicAdd(&gcnt, 1);
            g_groups[gi] = make_int4(b0 + k, min(GSZ, n - k), tid, 0);
        }
    }
    __syncthreads();
    if (tid == 0) g_ngroups = gcnt;
}

// ---------------------------------------------------------------------------
// Kernel 4: grouped span pooling. Block = group; 8 warps = 4 E-slices x 2 b.
// Each warp: 4 span accumulators (ESLICE=256 floats, 2 float4/lane).
// Per j: 2 row LDG.128 (x2 unroll) + 4 prob broadcasts + 32 FFMA, serving
// 4 spans at once -> row traffic cut ~4x and zero shfls in the hot loop.
// g_probs is zero beyond each span's width, so running to wmax is exact.
// ---------------------------------------------------------------------------
__global__ __launch_bounds__(256)
void main_kernel(const float* __restrict__ x,
                 const int* __restrict__ start,
                 const int* __restrict__ end,
                 float* __restrict__ out) {
    const int group = blockIdx.x;
    if (group >= g_ngroups) return;

    const int4 gd  = g_groups[group];     // base, cnt, t0, -
    const int base = gd.x, cnt = gd.y, t0 = gd.z;

    const int tid   = threadIdx.x;
    const int lane  = tid & 31;
    const int wi    = tid >> 5;
    const int b     = wi >> 2;            // 0..1
    const int slice = wi & 3;             // 0..3, 256 floats each

    int s[GSZ];
#pragma unroll
    for (int g = 0; g < GSZ; ++g)
        s[g] = g_sorted[base + min(g, cnt - 1)];

    // sorted ascending w within a t0 bin -> last member has wmax
    const int wmax = end[s[GSZ - 1]] - t0 + 1;

    const float4* __restrict__ xp =
        reinterpret_cast<const float4*>(x) + ((size_t)(b * TT + t0)) * 256 + slice * 64 + lane;
    const float* __restrict__ pb = g_probs + (size_t)b * SS * 32;

    float4 A0[GSZ], A1[GSZ];
#pragma unroll
    for (int g = 0; g < GSZ; ++g) {
        A0[g] = make_float4(0.f, 0.f, 0.f, 0.f);
        A1[g] = make_float4(0.f, 0.f, 0.f, 0.f);
    }

    int j = 0;
#pragma unroll 1
    for (; j + 2 <= wmax; j += 2) {
        const float4 r0 = __ldg(xp + (size_t)j * 256);
        const float4 r1 = __ldg(xp + (size_t)j * 256 + 32);
        const float4 q0 = __ldg(xp + (size_t)(j + 1) * 256);
        const float4 q1 = __ldg(xp + (size_t)(j + 1) * 256 + 32);
#pragma unroll
        for (int g = 0; g < GSZ; ++g) {
            const float p0 = __ldg(pb + (size_t)s[g] * 32 + j);
            const float p1 = __ldg(pb + (size_t)s[g] * 32 + j + 1);
            A0[g].x += p0 * r0.x + p1 * q0.x;
            A0[g].y += p0 * r0.y + p1 * q0.y;
            A0[g].z += p0 * r0.z + p1 * q0.z;
            A0[g].w += p0 * r0.w + p1 * q0.w;
            A1[g].x += p0 * r1.x + p1 * q1.x;
            A1[g].y += p0 * r1.y + p1 * q1.y;
            A1[g].z += p0 * r1.z + p1 * q1.z;
            A1[g].w += p0 * r1.w + p1 * q1.w;
        }
    }
    if (j < wmax) {
        const float4 r0 = __ldg(xp + (size_t)j * 256);
        const float4 r1 = __ldg(xp + (size_t)j * 256 + 32);
#pragma unroll
        for (int g = 0; g < GSZ; ++g) {
            const float p0 = __ldg(pb + (size_t)s[g] * 32 + j);
            A0[g].x += p0 * r0.x;  A0[g].y += p0 * r0.y;
            A0[g].z += p0 * r0.z;  A0[g].w += p0 * r0.w;
            A1[g].x += p0 * r1.x;  A1[g].y += p0 * r1.y;
            A1[g].z += p0 * r1.z;  A1[g].w += p0 * r1.w;
        }
    }

    float4* __restrict__ o4 = reinterpret_cast<float4*>(out);
#pragma unroll
    for (int g = 0; g < GSZ; ++g) {
        if (g < cnt) {
            const size_t off = ((size_t)b * SS + s[g]) * 256 + slice * 64 + lane;
            o4[off]      = A0[g];
            o4[off + 32] = A1[g];
        }
    }
}

// ---------------------------------------------------------------------------
// Launch
// Inputs (metadata order): x (B,T,E) f32, W (E,1) f32, b (1,) f32,
//                          start (S,) i32, end (S,) i32
// Output: (B, S, E) f32
// ---------------------------------------------------------------------------
extern "C" void kernel_launch(void* const* d_in, const int* in_sizes, int n_in,
                              void* d_out, int out_size) {
    const float* x     = (const float*)d_in[0];
    const float* W     = (const float*)d_in[1];
    const float* bias  = (const float*)d_in[2];
    const int*   start = (const int*)d_in[3];
    const int*   end   = (const int*)d_in[4];
    float*       out   = (float*)d_out;

    static bool attr_done = false;
    if (!attr_done) {
        cudaFuncSetAttribute(sort_kernel,
                             cudaFuncAttributeMaxDynamicSharedMemorySize,
                             NBINS * 4);
        attr_done = true;
    }

    score_kernel<<<(BB * TT) / 8, 256>>>(x, W, bias);
    prob_kernel<<<(BB * SS) / 8, 256>>>(start, end);
    sort_kernel<<<1, 1024, NBINS * 4>>>(start, end);
    main_kernel<<<NGROUPS_MAX, 256>>>(x, start, end, out);
}